// round 1
// baseline (speedup 1.0000x reference)
#include <cuda_runtime.h>
#include <math.h>

#define NT   365
#define NG   3000
#define NXI  20
#define HD   256
#define TM   20
#define NBLK (NG / TM)      /* 150, exact */
#define KTOT 512
#define KCH  8
#define NCH  (KTOT / KCH)   /* 64 */

// ---------------- persistent scratch (device globals; no allocation) --------
__device__ float g_WcT[KTOT][1024];   // k-major packed [w_ih | w_hh], 2 MB
__device__ float g_bc[1024];          // b_ih + b_hh
__device__ float g_h[NG][HD];
__device__ float g_c[NG][HD];
__device__ float g_yprev[NG];

// ---------------- init: pack weights + zero state ---------------------------
__global__ void init_kernel(const float* __restrict__ w_ih, const float* __restrict__ b_ih,
                            const float* __restrict__ w_hh, const float* __restrict__ b_hh)
{
    int idx = blockIdx.x * blockDim.x + threadIdx.x;
    int stride = gridDim.x * blockDim.x;
    for (int i = idx; i < KTOT * 1024; i += stride) {
        int k = i >> 10, col = i & 1023;
        g_WcT[k][col] = (k < HD) ? w_ih[col * HD + k] : w_hh[col * HD + (k - HD)];
    }
    for (int i = idx; i < 1024; i += stride) g_bc[i] = b_ih[i] + b_hh[i];
    float* hflat = &g_h[0][0];
    float* cflat = &g_c[0][0];
    for (int i = idx; i < NG * HD; i += stride) { hflat[i] = 0.f; cflat[i] = 0.f; }
    for (int i = idx; i < NG; i += stride) g_yprev[i] = 0.f;
}

// ---------------- helpers ---------------------------------------------------
__device__ __forceinline__ void cp16(float* dst, const float* src)
{
    unsigned d = (unsigned)__cvta_generic_to_shared(dst);
    asm volatile("cp.async.cg.shared.global [%0], [%1], 16;\n" :: "r"(d), "l"(src));
}

__device__ __forceinline__ void prefetch_chunk(float* Ws, int buf, int c, int tid)
{
    const int k0 = c * KCH;
    float* dst = Ws + buf * (KCH * 1024) + tid * 4;
    const float* src = &g_WcT[k0][tid * 4];
#pragma unroll
    for (int kk = 0; kk < KCH; kk++)
        cp16(dst + kk * 1024, src + kk * 1024);
    asm volatile("cp.async.commit_group;\n" ::: "memory");
}

__device__ __forceinline__ float sigm(float v) { return 1.f / (1.f + __expf(-v)); }

// ---------------- one LSTM timestep -----------------------------------------
// grid = 150 blocks x 256 threads; block b owns rows [b*20, b*20+20)
__global__ void __launch_bounds__(256, 1) step_kernel(
    int t,
    const float* __restrict__ x,     // [NT, NG, NXI]
    const float* __restrict__ y,     // [NT, NG, 1]
    const float* __restrict__ w_in,  // [HD, NXI+1]
    const float* __restrict__ b_in,  // [HD]
    const float* __restrict__ w_out, // [1, HD]
    const float* __restrict__ b_out, // [1]
    float* __restrict__ out)         // [NT, NG, 1]
{
    extern __shared__ float sm[];
    float* z_s   = sm;                      // [TM][512]  = x0 | h
    float* Ws    = z_s + TM * KTOT;         // [2][KCH][1024]  weight chunks
    float* win_s = Ws + 2 * KCH * 1024;     // [HD][21]
    float* x_s   = win_s + HD * 21;         // [TM][NXI]
    float* yt_s  = x_s + TM * NXI;          // [TM]
    float* red_s = yt_s + TM;               // [TM][2]

    const int tid = threadIdx.x;
    const int r0  = blockIdx.x * TM;

    // ---- stage inputs -------------------------------------------------------
    for (int i = tid; i < HD * 21; i += 256) win_s[i] = w_in[i];
    for (int i = tid; i < TM * NXI; i += 256) {
        int r = i / NXI, c = i % NXI;
        x_s[i] = x[((size_t)t * NG + (r0 + r)) * NXI + c];
    }
    if (tid < TM) {
        int row = r0 + tid;
        float yo = y[(size_t)t * NG + row];
        yt_s[tid] = (yo == yo) ? yo : g_yprev[row];   // fillObs
    }
    for (int i = tid; i < TM * HD; i += 256) {
        int r = i >> 8, j = i & 255;
        z_s[r * KTOT + HD + j] = g_h[r0 + r][j];
    }
    __syncthreads();

    // ---- input projection: x0 = relu([x,yt] @ w_in.T + b_in) ---------------
    {
        float wl[21];
#pragma unroll
        for (int k = 0; k < 21; k++) wl[k] = win_s[tid * 21 + k];
        float bj = b_in[tid];
#pragma unroll 4
        for (int r = 0; r < TM; r++) {
            float s = fmaf(yt_s[r], wl[20], bj);
#pragma unroll
            for (int k = 0; k < NXI; k++) s = fmaf(x_s[r * NXI + k], wl[k], s);
            z_s[r * KTOT + tid] = fmaxf(s, 0.f);
        }
    }
    __syncthreads();

    // ---- main GEMM: gates[20][1024] = z_s[20][512] @ WcT ------------------
    const int rg = tid >> 6;     // row group 0..3  (5 rows each)
    const int cg = tid & 63;     // col group 0..63 (4 hcols each)

    float acc[5][4][4];          // [row][gate][hcol]
#pragma unroll
    for (int g = 0; g < 4; g++) {
#pragma unroll
        for (int j = 0; j < 4; j++) {
            float b = g_bc[g * HD + cg * 4 + j];
#pragma unroll
            for (int i = 0; i < 5; i++) acc[i][g][j] = b;
        }
    }

    prefetch_chunk(Ws, 0, 0, tid);
    for (int c = 0; c < NCH; c++) {
        const int buf = c & 1;
        if (c + 1 < NCH) {
            prefetch_chunk(Ws, buf ^ 1, c + 1, tid);
            asm volatile("cp.async.wait_group 1;\n" ::: "memory");
        } else {
            asm volatile("cp.async.wait_group 0;\n" ::: "memory");
        }
        __syncthreads();

        const float* Wbuf = Ws + buf * (KCH * 1024);
        const int k0 = c * KCH;
#pragma unroll
        for (int kk = 0; kk < KCH; kk++) {
            const float* wrow = Wbuf + kk * 1024;
            float zv[5];
#pragma unroll
            for (int i = 0; i < 5; i++) zv[i] = z_s[(rg * 5 + i) * KTOT + k0 + kk];
#pragma unroll
            for (int g = 0; g < 4; g++) {
                float4 wv = *(const float4*)(wrow + g * HD + cg * 4);
#pragma unroll
                for (int i = 0; i < 5; i++) {
                    acc[i][g][0] = fmaf(zv[i], wv.x, acc[i][g][0]);
                    acc[i][g][1] = fmaf(zv[i], wv.y, acc[i][g][1]);
                    acc[i][g][2] = fmaf(zv[i], wv.z, acc[i][g][2]);
                    acc[i][g][3] = fmaf(zv[i], wv.w, acc[i][g][3]);
                }
            }
        }
        __syncthreads();
    }

    // ---- cell update + y projection ----------------------------------------
    const int lane = tid & 31;
    const int half = (tid >> 5) & 1;
    float wo[4];
#pragma unroll
    for (int j = 0; j < 4; j++) wo[j] = w_out[cg * 4 + j];

    float part[5];
#pragma unroll
    for (int i = 0; i < 5; i++) {
        int row = r0 + rg * 5 + i;
        float4 co = *(const float4*)&g_c[row][cg * 4];
        float cold[4] = {co.x, co.y, co.z, co.w};
        float cn[4], hn[4];
        float p = 0.f;
#pragma unroll
        for (int j = 0; j < 4; j++) {
            float ig = sigm(acc[i][0][j]);
            float fg = sigm(acc[i][1][j]);
            float gg = tanhf(acc[i][2][j]);
            float og = sigm(acc[i][3][j]);
            float cc = fmaf(fg, cold[j], ig * gg);
            float hh = og * tanhf(cc);
            cn[j] = cc; hn[j] = hh;
            p = fmaf(hh, wo[j], p);
        }
        *(float4*)&g_c[row][cg * 4] = make_float4(cn[0], cn[1], cn[2], cn[3]);
        *(float4*)&g_h[row][cg * 4] = make_float4(hn[0], hn[1], hn[2], hn[3]);
        part[i] = p;
    }

    // deterministic reduction: warp shuffle (32 lanes cover 128 hcols), then
    // two halves combined in smem.
#pragma unroll
    for (int i = 0; i < 5; i++) {
        float v = part[i];
        v += __shfl_down_sync(0xffffffffu, v, 16);
        v += __shfl_down_sync(0xffffffffu, v, 8);
        v += __shfl_down_sync(0xffffffffu, v, 4);
        v += __shfl_down_sync(0xffffffffu, v, 2);
        v += __shfl_down_sync(0xffffffffu, v, 1);
        if (lane == 0) red_s[(rg * 5 + i) * 2 + half] = v;
    }
    __syncthreads();

    if (tid < TM) {
        int row = r0 + tid;
        float yv = red_s[tid * 2] + red_s[tid * 2 + 1] + b_out[0];
        out[(size_t)t * NG + row] = yv;
        g_yprev[row] = yv;      // feeds fillObs at t+1
    }
}

// ---------------- launch -----------------------------------------------------
extern "C" void kernel_launch(void* const* d_in, const int* in_sizes, int n_in,
                              void* d_out, int out_size)
{
    const float* x     = (const float*)d_in[0];
    const float* y     = (const float*)d_in[1];
    const float* w_in  = (const float*)d_in[2];
    const float* b_in  = (const float*)d_in[3];
    const float* w_ih  = (const float*)d_in[4];
    const float* b_ih  = (const float*)d_in[5];
    const float* w_hh  = (const float*)d_in[6];
    const float* b_hh  = (const float*)d_in[7];
    const float* w_out = (const float*)d_in[8];
    const float* b_out = (const float*)d_in[9];
    float* out = (float*)d_out;
    (void)in_sizes; (void)n_in; (void)out_size;

    const size_t smem = (size_t)(TM * KTOT + 2 * KCH * 1024 + HD * 21 +
                                 TM * NXI + TM + 2 * TM) * sizeof(float);
    cudaFuncSetAttribute(step_kernel, cudaFuncAttributeMaxDynamicSharedMemorySize,
                         (int)smem);

    init_kernel<<<256, 256>>>(w_ih, b_ih, w_hh, b_hh);
    for (int t = 0; t < NT; t++)
        step_kernel<<<NBLK, 256, smem>>>(t, x, y, w_in, b_in, w_out, b_out, out);
}

// round 3
// speedup vs baseline: 1.0879x; 1.0879x over previous
#include <cuda_runtime.h>
#include <math.h>
#include <stdint.h>

#define NTT   365
#define NG    3000
#define NXI   20
#define HD    256
#define MROWS 3072               /* padded rows */
#define NMT   24                 /* M tiles of 128 */
#define NNT   4                  /* N tiles of 256 packed cols */
#define NKC   32                 /* K chunks of 16 (K=512) */
#define ABLK  4096               /* floats per (mtile,kc) A block: hi2048+lo2048 */
#define BBLK  8192               /* floats per (ntile,kc) B block: hi4096+lo4096 */
#define STG_FLOATS 12288         /* A 4096 + B 8192 */
#define NSTG  3
#define RED_OFF (NSTG * STG_FLOATS)              /* 36864 floats */
#define MB_OFF  ((RED_OFF + 512) * 4)            /* byte offset of mbarriers */
#define SMEM_BYTES (MB_OFF + 32)

// ---------------- persistent device globals ---------------------------------
__device__ float g_Wp[NNT * NKC * BBLK];   // fragment-ordered weights hi/lo (4.2MB)
__device__ float g_Zp[NMT * NKC * ABLK];   // fragment-ordered activations (12.6MB)
__device__ float g_bc[1024];               // b_ih + b_hh, ORIGINAL order
__device__ float g_h[MROWS * HD];
__device__ float g_c[MROWS * HD];
__device__ float g_ypart[NNT * MROWS];

// ---------------- helpers ----------------------------------------------------
__device__ __forceinline__ float tf32r(float a) {
    uint32_t u; asm("cvt.rna.tf32.f32 %0, %1;" : "=r"(u) : "f"(a));
    return __uint_as_float(u);
}
__device__ __forceinline__ float sigm(float v) { return 1.f / (1.f + __expf(-v)); }
__device__ __forceinline__ uint32_t smem_u32(const void* p) {
    uint32_t a;
    asm("{ .reg .u64 t; cvta.to.shared.u64 t, %1; cvt.u32.u64 %0, t; }" : "=r"(a) : "l"(p));
    return a;
}
__device__ __forceinline__ void mbar_init(uint32_t m, uint32_t cnt) {
    asm volatile("mbarrier.init.shared.b64 [%0], %1;" :: "r"(m), "r"(cnt) : "memory");
}
__device__ __forceinline__ void mbar_expect(uint32_t m, uint32_t b) {
    asm volatile("mbarrier.arrive.expect_tx.shared.b64 _, [%0], %1;" :: "r"(m), "r"(b) : "memory");
}
__device__ __forceinline__ void mbar_wait(uint32_t m, uint32_t ph) {
    asm volatile("{\n\t.reg .pred P;\nW1_%=:\n\t"
        "mbarrier.try_wait.parity.acquire.cta.shared::cta.b64 P, [%0], %1, 0x989680;\n\t"
        "@P bra W2_%=;\n\tbra W1_%=;\nW2_%=:\n\t}" :: "r"(m), "r"(ph) : "memory");
}
__device__ __forceinline__ void bulk_cp(uint32_t dst, const void* src, uint32_t bytes, uint32_t mbar) {
    asm volatile("cp.async.bulk.shared::cluster.global.mbarrier::complete_tx::bytes [%0], [%1], %2, [%3];"
        :: "r"(dst), "l"(src), "r"(bytes), "r"(mbar) : "memory");
}

#define MMA8(d, a, b) \
    asm volatile("mma.sync.aligned.m16n8k8.row.col.f32.tf32.tf32.f32 " \
        "{%0,%1,%2,%3}, {%4,%5,%6,%7}, {%8,%9}, {%0,%1,%2,%3};" \
        : "+f"((d)[0]), "+f"((d)[1]), "+f"((d)[2]), "+f"((d)[3]) \
        : "r"((a).x), "r"((a).y), "r"((a).z), "r"((a).w), \
          "r"((b).x), "r"((b).y))

// ---------------- init: pack weights into fragment order ---------------------
__global__ void init_kernel(const float* __restrict__ w_ih, const float* __restrict__ b_ih,
                            const float* __restrict__ w_hh, const float* __restrict__ b_hh)
{
    int idx = blockIdx.x * blockDim.x + threadIdx.x;
    int stride = gridDim.x * blockDim.x;
    for (int i = idx; i < 512 * 1024; i += stride) {
        int k = i >> 10, P = i & 1023;
        int kc = k >> 4, kk = k & 15, ks = kk >> 3, kp = kk & 7;
        int nC = P >> 8, w = (P >> 6) & 3, nt8 = (P >> 3) & 7, s = P & 7;
        int hcol = nC * 64 + w * 16 + (nt8 >> 2) * 8 + s;
        int j = (nt8 & 3) * 256 + hcol;               // original gate row
        float val = (k < 256) ? w_ih[j * 256 + k] : w_hh[j * 256 + (k - 256)];
        float hi = tf32r(val);
        float lo = tf32r(val - hi);
        int ntg = w * 8 + nt8;
        int lam = (s << 2) | (kp & 3);
        int off = ks * 2048 + ntg * 64 + lam * 2 + (kp >> 2);
        float* wb = g_Wp + (size_t)(nC * NKC + kc) * BBLK;
        wb[off] = hi;
        wb[4096 + off] = lo;
    }
    for (int i = idx; i < 1024; i += stride) g_bc[i] = b_ih[i] + b_hh[i];
    for (int i = idx; i < MROWS * HD; i += stride) { g_h[i] = 0.f; g_c[i] = 0.f; }
    for (int i = idx; i < NNT * MROWS; i += stride) g_ypart[i] = 0.f;
}

// ---------------- prep: z = [relu(Win.[x,yt]) | h] in fragment order ---------
// grid = 24 mtiles * 32 kchunks; 128 threads (one per row)
__global__ void __launch_bounds__(128) prep_kernel(
    int t, const float* __restrict__ x, const float* __restrict__ y,
    const float* __restrict__ w_in, const float* __restrict__ b_in,
    const float* __restrict__ b_out, float* __restrict__ out)
{
    __shared__ float wsl[16 * 21];
    __shared__ float bsl[16];
    int mt = blockIdx.x >> 5, kc = blockIdx.x & 31;
    int r = threadIdx.x;
    int gr = mt * 128 + r;
    bool valid = gr < NG;
    float* zb = g_Zp + (size_t)(mt * NKC + kc) * ABLK;

    int m = r & 15, m16 = r >> 4;
    float v[16];

    if (kc >= 16) {                              // h half of z
        int k0 = (kc - 16) * 16;
        const float* hrow = g_h + (size_t)gr * HD + k0;
        #pragma unroll
        for (int c = 0; c < 16; c++) v[c] = valid ? hrow[c] : 0.f;
    } else {                                     // x0 half: input projection
        for (int i = r; i < 16 * 21; i += 128) wsl[i] = w_in[kc * 16 * 21 + i];
        if (r < 16) bsl[r] = b_in[kc * 16 + r];
        float xv[NXI];
        float yt = 0.f;
        if (valid) {
            const float* xp = x + ((size_t)t * NG + gr) * NXI;
            #pragma unroll
            for (int d = 0; d < NXI; d++) xv[d] = xp[d];
            float yprev = 0.f;
            if (t > 0) {
                yprev = g_ypart[gr] + g_ypart[MROWS + gr] +
                        g_ypart[2 * MROWS + gr] + g_ypart[3 * MROWS + gr] + b_out[0];
                if (kc == 0) out[(size_t)(t - 1) * NG + gr] = yprev;
            }
            float yobs = y[(size_t)t * NG + gr];
            yt = (yobs == yobs) ? yobs : yprev;  // fillObs
        } else {
            #pragma unroll
            for (int d = 0; d < NXI; d++) xv[d] = 0.f;
        }
        __syncthreads();
        #pragma unroll
        for (int c = 0; c < 16; c++) {
            float s = bsl[c];
            const float* wr = &wsl[c * 21];
            #pragma unroll
            for (int d = 0; d < NXI; d++) s = fmaf(xv[d], wr[d], s);
            s = fmaf(yt, wr[20], s);
            v[c] = valid ? fmaxf(s, 0.f) : 0.f;
        }
    }

    #pragma unroll
    for (int c = 0; c < 16; c++) {
        int ks = c >> 3, kp = c & 7;
        int lam = ((m & 7) << 2) | (kp & 3);
        int a = ((kp >> 2) << 1) | (m >> 3);
        int off = ks * 1024 + m16 * 128 + lam * 4 + a;
        float hi = tf32r(v[c]);
        zb[off] = hi;
        zb[2048 + off] = tf32r(v[c] - hi);
    }
}

// ---------------- GEMM + LSTM cell: mma.sync tf32 3-pass ---------------------
// grid = 96 CTAs (24 M x 4 N), 256 threads (8 warps, 2M x 4N, warp tile 64x64)
__global__ void __launch_bounds__(256, 1) gemm_kernel(const float* __restrict__ w_out)
{
    extern __shared__ float sm[];
    uint32_t sb = smem_u32(sm);
    const int tid = threadIdx.x, wid = tid >> 5, lane = tid & 31;
    const int warpM = wid >> 2, warpN = wid & 3;
    const int nC = blockIdx.x & 3, mtb = blockIdx.x >> 2;

    uint32_t mb = sb + MB_OFF;
    if (tid == 0) { mbar_init(mb, 1); mbar_init(mb + 8, 1); mbar_init(mb + 16, 1); }
    __syncthreads();

    const float* Zbase = g_Zp + (size_t)mtb * NKC * ABLK;
    const float* Wbase = g_Wp + (size_t)nC * NKC * BBLK;

    if (tid == 0) {
        #pragma unroll
        for (int s = 0; s < NSTG; s++) {
            mbar_expect(mb + s * 8, 49152u);
            uint32_t as = sb + s * (STG_FLOATS * 4);
            bulk_cp(as, Zbase + (size_t)s * ABLK, 16384u, mb + s * 8);
            bulk_cp(as + 16384u, Wbase + (size_t)s * BBLK, 32768u, mb + s * 8);
        }
    }

    float acc[4][8][4];
    #pragma unroll
    for (int a = 0; a < 4; a++)
        #pragma unroll
        for (int b = 0; b < 8; b++)
            #pragma unroll
            for (int d = 0; d < 4; d++) acc[a][b][d] = 0.f;

    for (int ch = 0; ch < NKC; ch++) {
        int st = ch % NSTG;
        uint32_t ph = (uint32_t)((ch / NSTG) & 1);
        mbar_wait(mb + st * 8, ph);

        const float* stage = sm + st * STG_FLOATS;
        const uint4* Ab = (const uint4*)stage;
        const uint2* Bb = (const uint2*)(stage + 4096);

        #pragma unroll
        for (int ks = 0; ks < 2; ks++) {
            const uint4* Ah = Ab + ((ks * 1024 + warpM * 4 * 128 + lane * 4) >> 2);
            const uint2* Bh = Bb + ((ks * 2048 + warpN * 8 * 64 + lane * 2) >> 1);
            const uint2* Bl = Bh + 2048;
            uint4 ah[4];
            #pragma unroll
            for (int mt = 0; mt < 4; mt++) ah[mt] = Ah[mt * 32];
            #pragma unroll
            for (int nt = 0; nt < 8; nt++) {
                uint2 bh = Bh[nt * 32];
                uint2 bl = Bl[nt * 32];
                #pragma unroll
                for (int mt = 0; mt < 4; mt++) {
                    MMA8(acc[mt][nt], ah[mt], bh);
                    MMA8(acc[mt][nt], ah[mt], bl);
                }
            }
            uint4 al[4];
            #pragma unroll
            for (int mt = 0; mt < 4; mt++) al[mt] = Ah[512 + mt * 32];  // +2048 floats
            #pragma unroll
            for (int nt = 0; nt < 8; nt++) {
                uint2 bh = Bh[nt * 32];
                #pragma unroll
                for (int mt = 0; mt < 4; mt++) MMA8(acc[mt][nt], al[mt], bh);
            }
        }
        __syncthreads();
        if (tid == 0 && ch + NSTG < NKC) {
            int nx = ch + NSTG;
            mbar_expect(mb + st * 8, 49152u);
            uint32_t as = sb + st * (STG_FLOATS * 4);
            bulk_cp(as, Zbase + (size_t)nx * ABLK, 16384u, mb + st * 8);
            bulk_cp(as + 16384u, Wbase + (size_t)nx * BBLK, 32768u, mb + st * 8);
        }
    }

    // ---- epilogue: LSTM cell, thread-local gates ---------------------------
    const int q = lane & 3, rb = lane >> 2;
    float* red = sm + RED_OFF;   // [4 warpN][128 rows]

    #pragma unroll
    for (int mt = 0; mt < 4; mt++) {
        #pragma unroll
        for (int half = 0; half < 2; half++) {
            int row_local = warpM * 64 + mt * 16 + half * 8 + rb;
            int grow = mtb * 128 + row_local;
            float ysum = 0.f;
            #pragma unroll
            for (int hg = 0; hg < 2; hg++) {
                int hbase = nC * 64 + warpN * 16 + hg * 8 + 2 * q;
                float2 cold = *(const float2*)&g_c[(size_t)grow * HD + hbase];
                float coldv[2] = { cold.x, cold.y };
                float cn[2], hn[2];
                #pragma unroll
                for (int j = 0; j < 2; j++) {
                    int hcol = hbase + j;
                    int d = half * 2 + j;
                    float gi = acc[mt][hg * 4 + 0][d] + g_bc[hcol];
                    float gf = acc[mt][hg * 4 + 1][d] + g_bc[256 + hcol];
                    float gg = acc[mt][hg * 4 + 2][d] + g_bc[512 + hcol];
                    float go = acc[mt][hg * 4 + 3][d] + g_bc[768 + hcol];
                    float cc = fmaf(sigm(gf), coldv[j], sigm(gi) * tanhf(gg));
                    float hh = sigm(go) * tanhf(cc);
                    cn[j] = cc; hn[j] = hh;
                    ysum = fmaf(hh, __ldg(w_out + hcol), ysum);
                }
                *(float2*)&g_c[(size_t)grow * HD + hbase] = make_float2(cn[0], cn[1]);
                *(float2*)&g_h[(size_t)grow * HD + hbase] = make_float2(hn[0], hn[1]);
            }
            ysum += __shfl_xor_sync(0xffffffffu, ysum, 1);
            ysum += __shfl_xor_sync(0xffffffffu, ysum, 2);
            if (q == 0) red[warpN * 128 + row_local] = ysum;
        }
    }
    __syncthreads();
    if (tid < 128) {
        float s = red[tid] + red[128 + tid] + red[256 + tid] + red[384 + tid];
        g_ypart[nC * MROWS + mtb * 128 + tid] = s;
    }
}

// ---------------- finalize: out[NT-1] ----------------------------------------
__global__ void final_kernel(const float* __restrict__ b_out, float* __restrict__ out)
{
    int i = blockIdx.x * blockDim.x + threadIdx.x;
    if (i < NG) {
        float yv = g_ypart[i] + g_ypart[MROWS + i] +
                   g_ypart[2 * MROWS + i] + g_ypart[3 * MROWS + i] + b_out[0];
        out[(size_t)(NTT - 1) * NG + i] = yv;
    }
}

// ---------------- launch ------------------------------------------------------
extern "C" void kernel_launch(void* const* d_in, const int* in_sizes, int n_in,
                              void* d_out, int out_size)
{
    const float* x     = (const float*)d_in[0];
    const float* y     = (const float*)d_in[1];
    const float* w_in  = (const float*)d_in[2];
    const float* b_in  = (const float*)d_in[3];
    const float* w_ih  = (const float*)d_in[4];
    const float* b_ih  = (const float*)d_in[5];
    const float* w_hh  = (const float*)d_in[6];
    const float* b_hh  = (const float*)d_in[7];
    const float* w_out = (const float*)d_in[8];
    const float* b_out = (const float*)d_in[9];
    float* out = (float*)d_out;
    (void)in_sizes; (void)n_in; (void)out_size;

    cudaFuncSetAttribute(gemm_kernel, cudaFuncAttributeMaxDynamicSharedMemorySize,
                         SMEM_BYTES);

    init_kernel<<<512, 256>>>(w_ih, b_ih, w_hh, b_hh);
    for (int t = 0; t < NTT; t++) {
        prep_kernel<<<NMT * NKC, 128>>>(t, x, y, w_in, b_in, b_out, out);
        gemm_kernel<<<NMT * NNT, 256, SMEM_BYTES>>>(w_out);
    }
    final_kernel<<<(NG + 255) / 256, 256>>>(b_out, out);
}

// round 4
// speedup vs baseline: 1.6080x; 1.4781x over previous
#include <cuda_runtime.h>
#include <cuda_bf16.h>
#include <math.h>
#include <stdint.h>

#define NTT   365
#define NG    3000
#define NXI   20
#define HD    256
#define MROWS 3072               /* padded rows */
#define NMT   24                 /* M tiles of 128 */
#define NNT   4                  /* N tiles of 256 packed cols */
#define NKC   16                 /* K chunks of 32 (K=512) */
#define AB16  8192               /* bf16 units per A block (16KB: hi 8KB + lo 8KB) */
#define BB16  16384              /* bf16 units per B block (32KB: hi 16KB + lo 16KB) */
#define STG_BYTES 49152          /* A 16KB + B 32KB */
#define NSTG  3
#define RED_OFF_B (NSTG * STG_BYTES)     /* 147456 */
#define MB_OFF (RED_OFF_B + 2048)        /* 149504 */
#define SMEM_BYTES (MB_OFF + 32)

// ---------------- persistent device globals ---------------------------------
__device__ __nv_bfloat16 g_Wp[NNT * NKC * BB16];   // fragment-ordered weights (2MB)
__device__ __nv_bfloat16 g_Zp[NMT * NKC * AB16];   // fragment-ordered activations (6MB)
__device__ float g_bc[1024];
__device__ float g_h[MROWS * HD];
__device__ float g_c[MROWS * HD];
__device__ float g_ypart[NNT * MROWS];

// ---------------- helpers ----------------------------------------------------
__device__ __forceinline__ float sigm(float v) { return 1.f / (1.f + __expf(-v)); }
__device__ __forceinline__ uint32_t smem_u32(const void* p) {
    uint32_t a;
    asm("{ .reg .u64 t; cvta.to.shared.u64 t, %1; cvt.u32.u64 %0, t; }" : "=r"(a) : "l"(p));
    return a;
}
__device__ __forceinline__ void mbar_init(uint32_t m, uint32_t cnt) {
    asm volatile("mbarrier.init.shared.b64 [%0], %1;" :: "r"(m), "r"(cnt) : "memory");
}
__device__ __forceinline__ void mbar_expect(uint32_t m, uint32_t b) {
    asm volatile("mbarrier.arrive.expect_tx.shared.b64 _, [%0], %1;" :: "r"(m), "r"(b) : "memory");
}
__device__ __forceinline__ void mbar_wait(uint32_t m, uint32_t ph) {
    asm volatile("{\n\t.reg .pred P;\nW1_%=:\n\t"
        "mbarrier.try_wait.parity.acquire.cta.shared::cta.b64 P, [%0], %1, 0x989680;\n\t"
        "@P bra W2_%=;\n\tbra W1_%=;\nW2_%=:\n\t}" :: "r"(m), "r"(ph) : "memory");
}
__device__ __forceinline__ void bulk_cp(uint32_t dst, const void* src, uint32_t bytes, uint32_t mbar) {
    asm volatile("cp.async.bulk.shared::cluster.global.mbarrier::complete_tx::bytes [%0], [%1], %2, [%3];"
        :: "r"(dst), "l"(src), "r"(bytes), "r"(mbar) : "memory");
}

// bf16 m16n8k16 fragment encoding (row.col):
//  A reg r in {a0..a3}: r = (kk>=8)*2 + (rowlocal>=8); lane = (row%8)*4 + ((kk%8)>>1);
//                       16-bit slot = kk&1
//  B reg r in {b0,b1}:  r = kk>>3; lane = (col%8)*4 + ((kk%8)>>1); slot = kk&1
#define MMA16(d, a, b) \
    asm volatile("mma.sync.aligned.m16n8k16.row.col.f32.bf16.bf16.f32 " \
        "{%0,%1,%2,%3}, {%4,%5,%6,%7}, {%8,%9}, {%0,%1,%2,%3};" \
        : "+f"((d)[0]), "+f"((d)[1]), "+f"((d)[2]), "+f"((d)[3]) \
        : "r"((a).x), "r"((a).y), "r"((a).z), "r"((a).w), \
          "r"((b).x), "r"((b).y))

// ---------------- init: pack weights into fragment order ---------------------
__global__ void init_kernel(const float* __restrict__ w_ih, const float* __restrict__ b_ih,
                            const float* __restrict__ w_hh, const float* __restrict__ b_hh)
{
    int idx = blockIdx.x * blockDim.x + threadIdx.x;
    int stride = gridDim.x * blockDim.x;
    for (int i = idx; i < 512 * 1024; i += stride) {
        int k = i >> 10, P = i & 1023;
        int nC = P >> 8, Pl = P & 255;
        int wN = Pl >> 6, j = (Pl >> 3) & 7, s = Pl & 7;
        int hcol = nC * 64 + wN * 16 + (j >> 2) * 8 + s;
        int row = (j & 3) * 256 + hcol;                  // original gate row
        float val = (k < 256) ? w_ih[row * 256 + k] : w_hh[row * 256 + (k - 256)];
        __nv_bfloat16 hb = __float2bfloat16_rn(val);
        __nv_bfloat16 lb = __float2bfloat16_rn(val - __bfloat162float(hb));
        int ch = k >> 5, ks = (k >> 4) & 1, kk = k & 15;
        int nt = Pl >> 3;                                // 0..31
        int lane = s * 4 + ((kk & 7) >> 1);
        int u = ((ks * 32 + nt) * 32 + lane) * 4 + (kk >> 3) * 2 + (kk & 1);
        __nv_bfloat16* wb = g_Wp + (size_t)(nC * NKC + ch) * BB16;
        wb[u] = hb;
        wb[8192 + u] = lb;
    }
    for (int i = idx; i < 1024; i += stride) g_bc[i] = b_ih[i] + b_hh[i];
    for (int i = idx; i < MROWS * HD; i += stride) { g_h[i] = 0.f; g_c[i] = 0.f; }
    for (int i = idx; i < NNT * MROWS; i += stride) g_ypart[i] = 0.f;
}

// ---------------- prep: z = [relu(Win.[x,yt]) | h] in fragment order ---------
// grid = 24 mtiles * 16 kchunks; 128 threads (one per row)
__global__ void __launch_bounds__(128) prep_kernel(
    int t, const float* __restrict__ x, const float* __restrict__ y,
    const float* __restrict__ w_in, const float* __restrict__ b_in,
    const float* __restrict__ b_out, float* __restrict__ out)
{
    __shared__ __nv_bfloat16 stg[AB16];   // 16KB fragment staging
    __shared__ float wsl[32 * 21];
    __shared__ float bsl[32];
    int mt = blockIdx.x >> 4, kc = blockIdx.x & 15;
    int r = threadIdx.x;
    int gr = mt * 128 + r;
    bool valid = gr < NG;
    float v[32];

    if (kc >= 8) {                               // h half of z
        const float* hrow = g_h + (size_t)gr * HD + (kc - 8) * 32;
        #pragma unroll 8
        for (int c = 0; c < 32; c++) v[c] = valid ? hrow[c] : 0.f;
    } else {                                     // x0 half: input projection
        for (int i = r; i < 32 * 21; i += 128) wsl[i] = w_in[kc * 32 * 21 + i];
        if (r < 32) bsl[r] = b_in[kc * 32 + r];
        float xv[NXI];
        float yt = 0.f;
        if (valid) {
            const float* xp = x + ((size_t)t * NG + gr) * NXI;
            #pragma unroll
            for (int d = 0; d < NXI; d++) xv[d] = xp[d];
            float yprev = 0.f;
            if (t > 0) {
                yprev = g_ypart[gr] + g_ypart[MROWS + gr] +
                        g_ypart[2 * MROWS + gr] + g_ypart[3 * MROWS + gr] + b_out[0];
                if (kc == 0) out[(size_t)(t - 1) * NG + gr] = yprev;
            }
            float yobs = y[(size_t)t * NG + gr];
            yt = (yobs == yobs) ? yobs : yprev;  // fillObs
        } else {
            #pragma unroll
            for (int d = 0; d < NXI; d++) xv[d] = 0.f;
        }
        __syncthreads();
        #pragma unroll 4
        for (int c = 0; c < 32; c++) {
            float s = bsl[c];
            const float* wr = &wsl[c * 21];
            #pragma unroll
            for (int d = 0; d < NXI; d++) s = fmaf(xv[d], wr[d], s);
            s = fmaf(yt, wr[20], s);
            v[c] = valid ? fmaxf(s, 0.f) : 0.f;
        }
    }

    // pack into m16n8k16 A-fragment order
    int m16 = r >> 4, rl = r & 15, rq = rl & 7, half = rl >> 3;
    #pragma unroll
    for (int c = 0; c < 32; c++) {
        int ks = c >> 4, kk = c & 15;
        int lane = rq * 4 + ((kk & 7) >> 1);
        int reg = ((kk >> 3) << 1) + half;
        int u = ((ks * 8 + m16) * 32 + lane) * 8 + reg * 2 + (kk & 1);
        __nv_bfloat16 hb = __float2bfloat16_rn(v[c]);
        stg[u] = hb;
        stg[4096 + u] = __float2bfloat16_rn(v[c] - __bfloat162float(hb));
    }
    __syncthreads();
    const uint4* s4 = (const uint4*)stg;
    uint4* d4 = (uint4*)(g_Zp + (size_t)(mt * NKC + kc) * AB16);
    #pragma unroll
    for (int i = r; i < 1024; i += 128) d4[i] = s4[i];
}

// ---------------- GEMM + LSTM cell: mma.sync bf16 3-pass ---------------------
// grid = 96 CTAs (24 M x 4 N), 256 threads (8 warps, warp tile 64x64)
__global__ void __launch_bounds__(256, 1) gemm_kernel(const float* __restrict__ w_out)
{
    extern __shared__ float sm[];
    uint32_t sb = smem_u32(sm);
    const int tid = threadIdx.x, wid = tid >> 5, lane = tid & 31;
    const int warpM = wid >> 2, warpN = wid & 3;
    const int nC = blockIdx.x & 3, mtb = blockIdx.x >> 2;

    uint32_t mb = sb + MB_OFF;
    if (tid == 0) { mbar_init(mb, 1); mbar_init(mb + 8, 1); mbar_init(mb + 16, 1); }
    __syncthreads();

    const char* Zbase = (const char*)(g_Zp + (size_t)mtb * NKC * AB16);
    const char* Wbase = (const char*)(g_Wp + (size_t)nC * NKC * BB16);

    if (tid == 0) {
        #pragma unroll
        for (int s = 0; s < NSTG; s++) {
            mbar_expect(mb + s * 8, STG_BYTES);
            uint32_t as = sb + s * STG_BYTES;
            bulk_cp(as, Zbase + (size_t)s * 16384, 16384u, mb + s * 8);
            bulk_cp(as + 16384u, Wbase + (size_t)s * 32768, 32768u, mb + s * 8);
        }
    }

    float acc[4][8][4];
    #pragma unroll
    for (int a = 0; a < 4; a++)
        #pragma unroll
        for (int b = 0; b < 8; b++)
            #pragma unroll
            for (int d = 0; d < 4; d++) acc[a][b][d] = 0.f;

    for (int ch = 0; ch < NKC; ch++) {
        int st = ch % NSTG;
        uint32_t ph = (uint32_t)((ch / NSTG) & 1);
        mbar_wait(mb + st * 8, ph);
        const char* stg = (const char*)sm + st * STG_BYTES;

        #pragma unroll
        for (int ks = 0; ks < 2; ks++) {
            const uint4* Ahp = (const uint4*)(stg + ((ks * 8 + warpM * 4) * 32 + lane) * 16);
            uint4 ah[4], al[4];
            #pragma unroll
            for (int mt = 0; mt < 4; mt++) { ah[mt] = Ahp[mt * 32]; al[mt] = Ahp[512 + mt * 32]; }
            const uint2* Bhp = (const uint2*)(stg + 16384 + ((ks * 32 + warpN * 8) * 32 + lane) * 8);
            #pragma unroll
            for (int j = 0; j < 8; j++) {
                uint2 bh = Bhp[j * 32];
                uint2 bl = Bhp[2048 + j * 32];
                #pragma unroll
                for (int mt = 0; mt < 4; mt++) MMA16(acc[mt][j], ah[mt], bh);
                #pragma unroll
                for (int mt = 0; mt < 4; mt++) MMA16(acc[mt][j], al[mt], bh);
                #pragma unroll
                for (int mt = 0; mt < 4; mt++) MMA16(acc[mt][j], ah[mt], bl);
            }
        }
        __syncthreads();
        if (tid == 0 && ch + NSTG < NKC) {
            int nx = ch + NSTG;
            mbar_expect(mb + st * 8, STG_BYTES);
            uint32_t as = sb + st * STG_BYTES;
            bulk_cp(as, Zbase + (size_t)nx * 16384, 16384u, mb + st * 8);
            bulk_cp(as + 16384u, Wbase + (size_t)nx * 32768, 32768u, mb + st * 8);
        }
    }

    // ---- epilogue: LSTM cell, thread-local gates ---------------------------
    const int q = lane & 3, rb = lane >> 2;
    float* red = (float*)((char*)sm + RED_OFF_B);   // [4 warpN][128 rows]

    #pragma unroll
    for (int mt = 0; mt < 4; mt++) {
        #pragma unroll
        for (int half = 0; half < 2; half++) {
            int row_local = warpM * 64 + mt * 16 + half * 8 + rb;
            int grow = mtb * 128 + row_local;
            float ysum = 0.f;
            #pragma unroll
            for (int hg = 0; hg < 2; hg++) {
                int hbase = nC * 64 + warpN * 16 + hg * 8 + 2 * q;
                float2 cold = *(const float2*)&g_c[(size_t)grow * HD + hbase];
                float coldv[2] = { cold.x, cold.y };
                float cn[2], hn[2];
                #pragma unroll
                for (int j = 0; j < 2; j++) {
                    int hcol = hbase + j;
                    int d = half * 2 + j;
                    float gi = acc[mt][hg * 4 + 0][d] + g_bc[hcol];
                    float gf = acc[mt][hg * 4 + 1][d] + g_bc[256 + hcol];
                    float gg = acc[mt][hg * 4 + 2][d] + g_bc[512 + hcol];
                    float go = acc[mt][hg * 4 + 3][d] + g_bc[768 + hcol];
                    float cc = fmaf(sigm(gf), coldv[j], sigm(gi) * tanhf(gg));
                    float hh = sigm(go) * tanhf(cc);
                    cn[j] = cc; hn[j] = hh;
                    ysum = fmaf(hh, __ldg(w_out + hcol), ysum);
                }
                *(float2*)&g_c[(size_t)grow * HD + hbase] = make_float2(cn[0], cn[1]);
                *(float2*)&g_h[(size_t)grow * HD + hbase] = make_float2(hn[0], hn[1]);
            }
            ysum += __shfl_xor_sync(0xffffffffu, ysum, 1);
            ysum += __shfl_xor_sync(0xffffffffu, ysum, 2);
            if (q == 0) red[warpN * 128 + row_local] = ysum;
        }
    }
    __syncthreads();
    if (tid < 128) {
        float s = red[tid] + red[128 + tid] + red[256 + tid] + red[384 + tid];
        g_ypart[nC * MROWS + mtb * 128 + tid] = s;
    }
}

// ---------------- finalize: out[NT-1] ----------------------------------------
__global__ void final_kernel(const float* __restrict__ b_out, float* __restrict__ out)
{
    int i = blockIdx.x * blockDim.x + threadIdx.x;
    if (i < NG) {
        float yv = g_ypart[i] + g_ypart[MROWS + i] +
                   g_ypart[2 * MROWS + i] + g_ypart[3 * MROWS + i] + b_out[0];
        out[(size_t)(NTT - 1) * NG + i] = yv;
    }
}

// ---------------- launch ------------------------------------------------------
extern "C" void kernel_launch(void* const* d_in, const int* in_sizes, int n_in,
                              void* d_out, int out_size)
{
    const float* x     = (const float*)d_in[0];
    const float* y     = (const float*)d_in[1];
    const float* w_in  = (const float*)d_in[2];
    const float* b_in  = (const float*)d_in[3];
    const float* w_ih  = (const float*)d_in[4];
    const float* b_ih  = (const float*)d_in[5];
    const float* w_hh  = (const float*)d_in[6];
    const float* b_hh  = (const float*)d_in[7];
    const float* w_out = (const float*)d_in[8];
    const float* b_out = (const float*)d_in[9];
    float* out = (float*)d_out;
    (void)in_sizes; (void)n_in; (void)out_size;

    cudaFuncSetAttribute(gemm_kernel, cudaFuncAttributeMaxDynamicSharedMemorySize,
                         SMEM_BYTES);

    init_kernel<<<512, 256>>>(w_ih, b_ih, w_hh, b_hh);
    for (int t = 0; t < NTT; t++) {
        prep_kernel<<<NMT * NKC, 128>>>(t, x, y, w_in, b_in, b_out, out);
        gemm_kernel<<<NMT * NNT, 256, SMEM_BYTES>>>(w_out);
    }
    final_kernel<<<(NG + 255) / 256, 256>>>(b_out, out);
}

// round 5
// speedup vs baseline: 2.5499x; 1.5857x over previous
#include <cuda_runtime.h>
#include <cuda_fp16.h>
#include <math.h>
#include <stdint.h>

#define NTT   365
#define NG    3000
#define NXI   20
#define HD    256
#define MROWS 3072               /* padded rows */
#define NMT   24                 /* M tiles of 128 */
#define NNT   16                 /* N tiles of 64 packed cols */
#define NKC   16                 /* K chunks of 32 (K=512) */
#define ABH   4096               /* halfs per A block (8KB, single fp16) */
#define BBH   4096               /* halfs per B block (8KB: hi 4KB + lo 4KB) */
#define STG_BYTES 16384          /* A 8KB + B 8KB */
#define NSTG  3
#define RED_OFF_B (NSTG * STG_BYTES)     /* 49152 */
#define MB_OFF (RED_OFF_B + 1024)        /* 50176 */
#define SMEM_BYTES (MB_OFF + 32)

// ---------------- persistent device globals ---------------------------------
__device__ __half g_Wp[NNT * NKC * BBH];   // fragment-ordered weights hi/lo (2MB)
__device__ __half g_Zp[NMT * NKC * ABH];   // fragment-ordered activations (3MB)
__device__ float g_bc[1024];
__device__ float g_h[MROWS * HD];
__device__ float g_c[MROWS * HD];
__device__ float g_ypart[NNT * MROWS];

// ---------------- helpers ----------------------------------------------------
__device__ __forceinline__ float sigm(float v) { return 1.f / (1.f + __expf(-v)); }
__device__ __forceinline__ uint32_t smem_u32(const void* p) {
    uint32_t a;
    asm("{ .reg .u64 t; cvta.to.shared.u64 t, %1; cvt.u32.u64 %0, t; }" : "=r"(a) : "l"(p));
    return a;
}
__device__ __forceinline__ void mbar_init(uint32_t m, uint32_t cnt) {
    asm volatile("mbarrier.init.shared.b64 [%0], %1;" :: "r"(m), "r"(cnt) : "memory");
}
__device__ __forceinline__ void mbar_expect(uint32_t m, uint32_t b) {
    asm volatile("mbarrier.arrive.expect_tx.shared.b64 _, [%0], %1;" :: "r"(m), "r"(b) : "memory");
}
__device__ __forceinline__ void mbar_wait(uint32_t m, uint32_t ph) {
    asm volatile("{\n\t.reg .pred P;\nW1_%=:\n\t"
        "mbarrier.try_wait.parity.acquire.cta.shared::cta.b64 P, [%0], %1, 0x989680;\n\t"
        "@P bra W2_%=;\n\tbra W1_%=;\nW2_%=:\n\t}" :: "r"(m), "r"(ph) : "memory");
}
__device__ __forceinline__ void bulk_cp(uint32_t dst, const void* src, uint32_t bytes, uint32_t mbar) {
    asm volatile("cp.async.bulk.shared::cluster.global.mbarrier::complete_tx::bytes [%0], [%1], %2, [%3];"
        :: "r"(dst), "l"(src), "r"(bytes), "r"(mbar) : "memory");
}

// fp16 m16n8k16 fragment encoding (row.col), validated in round 4 (same as bf16):
//  A reg: r = (kk>=8)*2 + (row>=8); lane = (row%8)*4 + ((kk%8)>>1); slot = kk&1
//  B reg: r = kk>>3; lane = (col%8)*4 + ((kk%8)>>1); slot = kk&1
#define MMA16(d, a, b) \
    asm volatile("mma.sync.aligned.m16n8k16.row.col.f32.f16.f16.f32 " \
        "{%0,%1,%2,%3}, {%4,%5,%6,%7}, {%8,%9}, {%0,%1,%2,%3};" \
        : "+f"((d)[0]), "+f"((d)[1]), "+f"((d)[2]), "+f"((d)[3]) \
        : "r"((a).x), "r"((a).y), "r"((a).z), "r"((a).w), \
          "r"((b).x), "r"((b).y))

// ---------------- init: pack weights (fp16 hi/lo) into fragment order --------
// Packed col P (0..1023): nC = P>>6; Pt = P&63; warpN = Pt>>5; Pl = Pt&31;
// j = Pl>>3, s = Pl&7, q = s>>1, e = s&1; hl = q*2 + (j>>1); gate = (j&1)*2 + e;
// hcol = nC*16 + warpN*8 + hl; original gate row = gate*256 + hcol.
__global__ void init_kernel(const float* __restrict__ w_ih, const float* __restrict__ b_ih,
                            const float* __restrict__ w_hh, const float* __restrict__ b_hh)
{
    int idx = blockIdx.x * blockDim.x + threadIdx.x;
    int stride = gridDim.x * blockDim.x;
    for (int i = idx; i < 512 * 1024; i += stride) {
        int k = i >> 10, P = i & 1023;
        int nC = P >> 6, Pt = P & 63;
        int wN = Pt >> 5, Pl = Pt & 31;
        int j = Pl >> 3, s = Pl & 7, q = s >> 1, e = s & 1;
        int hl = q * 2 + (j >> 1);
        int gate = (j & 1) * 2 + e;
        int hcol = nC * 16 + wN * 8 + hl;
        int row = gate * 256 + hcol;
        float val = (k < 256) ? w_ih[row * 256 + k] : w_hh[row * 256 + (k - 256)];
        __half hb = __float2half_rn(val);
        __half lb = __float2half_rn(val - __half2float(hb));
        int ch = k >> 5, ks = (k >> 4) & 1, kk = k & 15;
        int nt8 = Pt >> 3;                               // 0..7
        int lane = s * 4 + ((kk & 7) >> 1);
        int u = ((ks * 8 + nt8) * 32 + lane) * 4 + (kk >> 3) * 2 + (kk & 1);
        __half* wb = g_Wp + (size_t)(nC * NKC + ch) * BBH;
        wb[u] = hb;
        wb[2048 + u] = lb;
    }
    for (int i = idx; i < 1024; i += stride) g_bc[i] = b_ih[i] + b_hh[i];
    for (int i = idx; i < MROWS * HD; i += stride) { g_h[i] = 0.f; g_c[i] = 0.f; }
    for (int i = idx; i < NNT * MROWS; i += stride) g_ypart[i] = 0.f;
}

// ---------------- prep: z = [relu(Win.[x,yt]) | h] as single-fp16 fragments --
// grid = 24 mtiles * 16 kchunks; 128 threads (one per row)
__global__ void __launch_bounds__(128) prep_kernel(
    int t, const float* __restrict__ x, const float* __restrict__ y,
    const float* __restrict__ w_in, const float* __restrict__ b_in,
    const float* __restrict__ b_out, float* __restrict__ out)
{
    __shared__ __half stg[ABH];           // 8KB fragment staging
    __shared__ float wsl[32 * 21];
    __shared__ float bsl[32];
    int mt = blockIdx.x >> 4, kc = blockIdx.x & 15;
    int r = threadIdx.x;
    int gr = mt * 128 + r;
    bool valid = gr < NG;
    float v[32];

    if (kc >= 8) {                               // h half of z
        const float* hrow = g_h + (size_t)gr * HD + (kc - 8) * 32;
        #pragma unroll 8
        for (int c = 0; c < 32; c++) v[c] = valid ? hrow[c] : 0.f;
    } else {                                     // x0 half: input projection
        for (int i = r; i < 32 * 21; i += 128) wsl[i] = w_in[kc * 32 * 21 + i];
        if (r < 32) bsl[r] = b_in[kc * 32 + r];
        float xv[NXI];
        float yt = 0.f;
        if (valid) {
            const float* xp = x + ((size_t)t * NG + gr) * NXI;
            #pragma unroll
            for (int d = 0; d < NXI; d++) xv[d] = xp[d];
            float yprev = 0.f;
            if (t > 0) {
                #pragma unroll
                for (int n = 0; n < NNT; n++) yprev += g_ypart[n * MROWS + gr];
                yprev += b_out[0];
                if (kc == 0) out[(size_t)(t - 1) * NG + gr] = yprev;
            }
            float yobs = y[(size_t)t * NG + gr];
            yt = (yobs == yobs) ? yobs : yprev;  // fillObs
        } else {
            #pragma unroll
            for (int d = 0; d < NXI; d++) xv[d] = 0.f;
        }
        __syncthreads();
        #pragma unroll 4
        for (int c = 0; c < 32; c++) {
            float s = bsl[c];
            const float* wr = &wsl[c * 21];
            #pragma unroll
            for (int d = 0; d < NXI; d++) s = fmaf(xv[d], wr[d], s);
            s = fmaf(yt, wr[20], s);
            v[c] = valid ? fmaxf(s, 0.f) : 0.f;
        }
    }

    // pack into m16n8k16 A-fragment order (single fp16)
    int m16 = r >> 4, rl = r & 15, rq = rl & 7, half = rl >> 3;
    #pragma unroll
    for (int c = 0; c < 32; c++) {
        int ks = c >> 4, kk = c & 15;
        int lane = rq * 4 + ((kk & 7) >> 1);
        int reg = ((kk >> 3) << 1) + half;
        int u = ((ks * 8 + m16) * 32 + lane) * 8 + reg * 2 + (kk & 1);
        stg[u] = __float2half_rn(v[c]);
    }
    __syncthreads();
    const uint4* s4 = (const uint4*)stg;
    uint4* d4 = (uint4*)(g_Zp + (size_t)(mt * NKC + kc) * ABH);
    #pragma unroll
    for (int i = r; i < 512; i += 128) d4[i] = s4[i];
}

// ---------------- GEMM + LSTM cell: mma.sync fp16 2-pass ---------------------
// grid = 384 CTAs (24 M x 16 N), 128 threads (4 warps: 2M x 2N, warp 64x32)
__global__ void __launch_bounds__(128) gemm_kernel(const float* __restrict__ w_out)
{
    extern __shared__ float sm[];
    uint32_t sb = smem_u32(sm);
    const int tid = threadIdx.x, wid = tid >> 5, lane = tid & 31;
    const int warpM = wid >> 1, warpN = wid & 1;
    const int nC = blockIdx.x & 15, mtb = blockIdx.x >> 4;

    uint32_t mb = sb + MB_OFF;
    if (tid == 0) { mbar_init(mb, 1); mbar_init(mb + 8, 1); mbar_init(mb + 16, 1); }
    __syncthreads();

    const char* Zbase = (const char*)(g_Zp + (size_t)mtb * NKC * ABH);
    const char* Wbase = (const char*)(g_Wp + (size_t)nC * NKC * BBH);

    if (tid == 0) {
        #pragma unroll
        for (int s = 0; s < NSTG; s++) {
            mbar_expect(mb + s * 8, STG_BYTES);
            uint32_t as = sb + s * STG_BYTES;
            bulk_cp(as, Zbase + (size_t)s * 8192, 8192u, mb + s * 8);
            bulk_cp(as + 8192u, Wbase + (size_t)s * 8192, 8192u, mb + s * 8);
        }
    }

    float acc[4][4][4];
    #pragma unroll
    for (int a = 0; a < 4; a++)
        #pragma unroll
        for (int b = 0; b < 4; b++)
            #pragma unroll
            for (int d = 0; d < 4; d++) acc[a][b][d] = 0.f;

    for (int ch = 0; ch < NKC; ch++) {
        int st = ch % NSTG;
        uint32_t ph = (uint32_t)((ch / NSTG) & 1);
        mbar_wait(mb + st * 8, ph);
        const char* stg = (const char*)sm + st * STG_BYTES;

        #pragma unroll
        for (int ks = 0; ks < 2; ks++) {
            const uint4* Ap = (const uint4*)(stg + ((ks * 8 + warpM * 4) * 32 + lane) * 16);
            uint4 a[4];
            #pragma unroll
            for (int mt = 0; mt < 4; mt++) a[mt] = Ap[mt * 32];
            const uint2* Bp = (const uint2*)(stg + 8192 + ((ks * 8 + warpN * 4) * 32 + lane) * 8);
            #pragma unroll
            for (int j = 0; j < 4; j++) {
                uint2 bh = Bp[j * 32];
                uint2 bl = Bp[512 + j * 32];
                #pragma unroll
                for (int mt = 0; mt < 4; mt++) MMA16(acc[mt][j], a[mt], bh);
                #pragma unroll
                for (int mt = 0; mt < 4; mt++) MMA16(acc[mt][j], a[mt], bl);
            }
        }
        __syncthreads();
        if (tid == 0 && ch + NSTG < NKC) {
            int nx = ch + NSTG;
            mbar_expect(mb + st * 8, STG_BYTES);
            uint32_t as = sb + st * STG_BYTES;
            bulk_cp(as, Zbase + (size_t)nx * 8192, 8192u, mb + st * 8);
            bulk_cp(as + 8192u, Wbase + (size_t)nx * 8192, 8192u, mb + st * 8);
        }
    }

    // ---- epilogue: LSTM cell, thread-local gates ---------------------------
    const int q = lane & 3, rb = lane >> 2;
    float* red = (float*)((char*)sm + RED_OFF_B);   // [2 warpN][128 rows]

    #pragma unroll
    for (int mt = 0; mt < 4; mt++) {
        #pragma unroll
        for (int half = 0; half < 2; half++) {
            int row_local = warpM * 64 + mt * 16 + half * 8 + rb;
            int grow = mtb * 128 + row_local;
            int hbase = nC * 16 + warpN * 8 + 2 * q;
            float2 cold = *(const float2*)&g_c[(size_t)grow * HD + hbase];
            float coldv[2] = { cold.x, cold.y };
            float cn[2], hn[2];
            float ysum = 0.f;
            #pragma unroll
            for (int jj = 0; jj < 2; jj++) {
                int hcol = hbase + jj;
                float gi = acc[mt][jj * 2 + 0][half * 2 + 0] + g_bc[hcol];
                float gf = acc[mt][jj * 2 + 0][half * 2 + 1] + g_bc[256 + hcol];
                float gg = acc[mt][jj * 2 + 1][half * 2 + 0] + g_bc[512 + hcol];
                float go = acc[mt][jj * 2 + 1][half * 2 + 1] + g_bc[768 + hcol];
                float cc = fmaf(sigm(gf), coldv[jj], sigm(gi) * tanhf(gg));
                float hh = sigm(go) * tanhf(cc);
                cn[jj] = cc; hn[jj] = hh;
                ysum = fmaf(hh, __ldg(w_out + hcol), ysum);
            }
            *(float2*)&g_c[(size_t)grow * HD + hbase] = make_float2(cn[0], cn[1]);
            *(float2*)&g_h[(size_t)grow * HD + hbase] = make_float2(hn[0], hn[1]);
            ysum += __shfl_xor_sync(0xffffffffu, ysum, 1);
            ysum += __shfl_xor_sync(0xffffffffu, ysum, 2);
            if (q == 0) red[warpN * 128 + row_local] = ysum;
        }
    }
    __syncthreads();
    if (tid < 128) {
        float s = red[tid] + red[128 + tid];
        g_ypart[nC * MROWS + mtb * 128 + tid] = s;
    }
}

// ---------------- finalize: out[NT-1] ----------------------------------------
__global__ void final_kernel(const float* __restrict__ b_out, float* __restrict__ out)
{
    int i = blockIdx.x * blockDim.x + threadIdx.x;
    if (i < NG) {
        float yv = b_out[0];
        #pragma unroll
        for (int n = 0; n < NNT; n++) yv += g_ypart[n * MROWS + i];
        out[(size_t)(NTT - 1) * NG + i] = yv;
    }
}

// ---------------- launch ------------------------------------------------------
extern "C" void kernel_launch(void* const* d_in, const int* in_sizes, int n_in,
                              void* d_out, int out_size)
{
    const float* x     = (const float*)d_in[0];
    const float* y     = (const float*)d_in[1];
    const float* w_in  = (const float*)d_in[2];
    const float* b_in  = (const float*)d_in[3];
    const float* w_ih  = (const float*)d_in[4];
    const float* b_ih  = (const float*)d_in[5];
    const float* w_hh  = (const float*)d_in[6];
    const float* b_hh  = (const float*)d_in[7];
    const float* w_out = (const float*)d_in[8];
    const float* b_out = (const float*)d_in[9];
    float* out = (float*)d_out;
    (void)in_sizes; (void)n_in; (void)out_size;

    cudaFuncSetAttribute(gemm_kernel, cudaFuncAttributeMaxDynamicSharedMemorySize,
                         SMEM_BYTES);

    init_kernel<<<512, 256>>>(w_ih, b_ih, w_hh, b_hh);
    for (int t = 0; t < NTT; t++) {
        prep_kernel<<<NMT * NKC, 128>>>(t, x, y, w_in, b_in, b_out, out);
        gemm_kernel<<<NMT * NNT, 128, SMEM_BYTES>>>(w_out);
    }
    final_kernel<<<(NG + 255) / 256, 256>>>(b_out, out);
}

// round 6
// speedup vs baseline: 2.5946x; 1.0176x over previous
#include <cuda_runtime.h>
#include <cuda_fp16.h>
#include <math.h>
#include <stdint.h>

#define NTT   365
#define NG    3000
#define NXI   20
#define HD    256
#define MROWS 3072               /* padded rows */
#define NMT   24                 /* M tiles of 128 */
#define NNT   16                 /* N tiles of 64 packed cols */
#define NKC   16                 /* K chunks of 32 (K=512) */
#define ABH   4096               /* halfs per A block (8KB, single fp16) */
#define BBH   4096               /* halfs per B block (8KB: hi 4KB + lo 4KB) */
#define ZXN   (NMT * 8 * ABH)    /* x-half fragment pool */
#define ZHN   (NMT * 8 * ABH)    /* h-half fragment pool (per parity buffer) */
#define UBN   ((size_t)NTT * NG * 256)
#define RB_PER_T 94              /* ceil(3000/32) row blocks for ubase */
#define STG_BYTES 16384          /* A 8KB + B 8KB */
#define NSTG  3
#define RED_OFF_B (NSTG * STG_BYTES)     /* 49152 */
#define MB_OFF (RED_OFF_B + 1024)        /* 50176 */
#define SMEM_BYTES (MB_OFF + 32)

// ---------------- persistent device globals ---------------------------------
__device__ __half g_Wp[NNT * NKC * BBH];   // fragment-ordered weights hi/lo (2MB)
__device__ __half g_Zx[ZXN];               // x0 fragments (prep-written, 1.5MB)
__device__ __half g_Zh[2 * ZHN];           // h fragments, double-buffered (3MB)
__device__ __half g_ub[UBN];               // ubase = Win_x.x + b_in, all t (561MB)
__device__ float g_bc[1024];
__device__ float g_winy[256];              // w_in[:,20]
__device__ float g_c[MROWS * HD];
__device__ float g_ypart[NNT * MROWS];

// ---------------- helpers ----------------------------------------------------
__device__ __forceinline__ float sigm(float v) { return 1.f / (1.f + __expf(-v)); }
__device__ __forceinline__ uint32_t smem_u32(const void* p) {
    uint32_t a;
    asm("{ .reg .u64 t; cvta.to.shared.u64 t, %1; cvt.u32.u64 %0, t; }" : "=r"(a) : "l"(p));
    return a;
}
__device__ __forceinline__ void mbar_init(uint32_t m, uint32_t cnt) {
    asm volatile("mbarrier.init.shared.b64 [%0], %1;" :: "r"(m), "r"(cnt) : "memory");
}
__device__ __forceinline__ void mbar_expect(uint32_t m, uint32_t b) {
    asm volatile("mbarrier.arrive.expect_tx.shared.b64 _, [%0], %1;" :: "r"(m), "r"(b) : "memory");
}
__device__ __forceinline__ void mbar_wait(uint32_t m, uint32_t ph) {
    asm volatile("{\n\t.reg .pred P;\nW1_%=:\n\t"
        "mbarrier.try_wait.parity.acquire.cta.shared::cta.b64 P, [%0], %1, 0x989680;\n\t"
        "@P bra W2_%=;\n\tbra W1_%=;\nW2_%=:\n\t}" :: "r"(m), "r"(ph) : "memory");
}
__device__ __forceinline__ void bulk_cp(uint32_t dst, const void* src, uint32_t bytes, uint32_t mbar) {
    asm volatile("cp.async.bulk.shared::cluster.global.mbarrier::complete_tx::bytes [%0], [%1], %2, [%3];"
        :: "r"(dst), "l"(src), "r"(bytes), "r"(mbar) : "memory");
}

// fp16 m16n8k16 fragment encoding (row.col), validated rounds 4-5:
//  A reg: r = (kk>=8)*2 + (row>=8); lane = (row%8)*4 + ((kk%8)>>1); slot = kk&1
//  B reg: r = kk>>3; lane = (col%8)*4 + ((kk%8)>>1); slot = kk&1
#define MMA16(d, a, b) \
    asm volatile("mma.sync.aligned.m16n8k16.row.col.f32.f16.f16.f32 " \
        "{%0,%1,%2,%3}, {%4,%5,%6,%7}, {%8,%9}, {%0,%1,%2,%3};" \
        : "+f"((d)[0]), "+f"((d)[1]), "+f"((d)[2]), "+f"((d)[3]) \
        : "r"((a).x), "r"((a).y), "r"((a).z), "r"((a).w), \
          "r"((b).x), "r"((b).y))

// fp16-accumulator variant for the lo pass: D/C = {d0,d1}, d0 = (c0,c1), d1 = (c2,c3)
#define MMA16H(d, a, b) \
    asm volatile("mma.sync.aligned.m16n8k16.row.col.f16.f16.f16.f16 " \
        "{%0,%1}, {%2,%3,%4,%5}, {%6,%7}, {%0,%1};" \
        : "+r"((d).x), "+r"((d).y) \
        : "r"((a).x), "r"((a).y), "r"((a).z), "r"((a).w), \
          "r"((b).x), "r"((b).y))

// ---------------- init: pack weights (fp16 hi/lo) into fragment order --------
__global__ void init_kernel(const float* __restrict__ w_ih, const float* __restrict__ b_ih,
                            const float* __restrict__ w_hh, const float* __restrict__ b_hh,
                            const float* __restrict__ w_in)
{
    int idx = blockIdx.x * blockDim.x + threadIdx.x;
    int stride = gridDim.x * blockDim.x;
    for (int i = idx; i < 512 * 1024; i += stride) {
        int k = i >> 10, P = i & 1023;
        int nC = P >> 6, Pt = P & 63;
        int wN = Pt >> 5, Pl = Pt & 31;
        int j = Pl >> 3, s = Pl & 7, q = s >> 1, e = s & 1;
        int hl = q * 2 + (j >> 1);
        int gate = (j & 1) * 2 + e;
        int hcol = nC * 16 + wN * 8 + hl;
        int row = gate * 256 + hcol;
        float val = (k < 256) ? w_ih[row * 256 + k] : w_hh[row * 256 + (k - 256)];
        __half hb = __float2half_rn(val);
        __half lb = __float2half_rn(val - __half2float(hb));
        int ch = k >> 5, ks = (k >> 4) & 1, kk = k & 15;
        int nt8 = Pt >> 3;
        int lane = s * 4 + ((kk & 7) >> 1);
        int u = ((ks * 8 + nt8) * 32 + lane) * 4 + (kk >> 3) * 2 + (kk & 1);
        __half* wb = g_Wp + (size_t)(nC * NKC + ch) * BBH;
        wb[u] = hb;
        wb[2048 + u] = lb;
    }
    for (int i = idx; i < 1024; i += stride) g_bc[i] = b_ih[i] + b_hh[i];
    for (int i = idx; i < 256; i += stride) g_winy[i] = w_in[i * 21 + 20];
    for (int i = idx; i < MROWS * HD; i += stride) g_c[i] = 0.f;
    for (int i = idx; i < NNT * MROWS; i += stride) g_ypart[i] = 0.f;
    uint32_t* zh = (uint32_t*)g_Zh;
    for (int i = idx; i < ZHN; i += stride) zh[i] = 0u;   // both buffers (2*ZHN halfs)
}

// ---------------- ubase: Win_x . x + b_in for ALL timesteps ------------------
// grid = 365 * 94 blocks, 256 threads; block = (t, 32-row slab); thread = col
__global__ void __launch_bounds__(256) ubase_kernel(
    const float* __restrict__ x, const float* __restrict__ w_in,
    const float* __restrict__ b_in)
{
    __shared__ float wsm[256 * 21];
    __shared__ float xsm[32 * NXI];
    int b = blockIdx.x;
    int t = b / RB_PER_T, rb = b % RB_PER_T;
    int r0 = rb * 32;
    int tid = threadIdx.x;
    for (int i = tid; i < 256 * 21; i += 256) wsm[i] = w_in[i];
    for (int i = tid; i < 32 * NXI; i += 256) {
        int rr = i / NXI, d = i % NXI;
        int row = r0 + rr;
        xsm[i] = (row < NG) ? x[((size_t)t * NG + row) * NXI + d] : 0.f;
    }
    __syncthreads();
    int col = tid;
    float w[NXI];
    #pragma unroll
    for (int d = 0; d < NXI; d++) w[d] = wsm[col * 21 + d];
    float bb = b_in[col];
    #pragma unroll 2
    for (int rr = 0; rr < 32; rr++) {
        int row = r0 + rr;
        if (row >= NG) break;
        float s = bb;
        #pragma unroll
        for (int d = 0; d < NXI; d++) s = fmaf(xsm[rr * NXI + d], w[d], s);
        g_ub[((size_t)t * NG + row) * 256 + col] = __float2half_rn(s);
    }
}

// ---------------- prep: x0 = relu(ubase + yt*winy) as fragments --------------
// grid = 24 mtiles * 8 kchunks; 128 threads (one per row)
__global__ void __launch_bounds__(128) prep_kernel(
    int t, const float* __restrict__ y, const float* __restrict__ b_out,
    float* __restrict__ out)
{
    __shared__ __half stg[ABH];
    int mt = blockIdx.x >> 3, kc = blockIdx.x & 7;
    int r = threadIdx.x;
    int gr = mt * 128 + r;
    bool valid = gr < NG;
    float v[32];

    float yt = 0.f;
    if (valid) {
        float yprev = 0.f;
        if (t > 0) {
            #pragma unroll
            for (int n = 0; n < NNT; n++) yprev += g_ypart[n * MROWS + gr];
            yprev += b_out[0];
            if (kc == 0) out[(size_t)(t - 1) * NG + gr] = yprev;
        }
        float yobs = y[(size_t)t * NG + gr];
        yt = (yobs == yobs) ? yobs : yprev;      // fillObs
        const __half* up = g_ub + ((size_t)t * NG + gr) * 256 + kc * 32;
        #pragma unroll
        for (int c = 0; c < 32; c++)
            v[c] = fmaxf(__half2float(up[c]) + yt * g_winy[kc * 32 + c], 0.f);
    } else {
        #pragma unroll
        for (int c = 0; c < 32; c++) v[c] = 0.f;
    }

    // pack into m16n8k16 A-fragment order (single fp16)
    int m16 = r >> 4, rl = r & 15, rq = rl & 7, half = rl >> 3;
    #pragma unroll
    for (int c = 0; c < 32; c++) {
        int ks = c >> 4, kk = c & 15;
        int lane = rq * 4 + ((kk & 7) >> 1);
        int reg = ((kk >> 3) << 1) + half;
        int u = ((ks * 8 + m16) * 32 + lane) * 8 + reg * 2 + (kk & 1);
        stg[u] = __float2half_rn(v[c]);
    }
    __syncthreads();
    const uint4* s4 = (const uint4*)stg;
    uint4* d4 = (uint4*)(g_Zx + (size_t)(mt * 8 + kc) * ABH);
    #pragma unroll
    for (int i = r; i < 512; i += 128) d4[i] = s4[i];
}

// ---------------- GEMM + LSTM cell: fp16 2-pass (hi f32acc, lo f16acc) -------
// grid = 384 CTAs (24 M x 16 N), 128 threads (4 warps: 2M x 2N, warp 64x32)
__global__ void __launch_bounds__(128) gemm_kernel(int t, const float* __restrict__ w_out)
{
    extern __shared__ float sm[];
    uint32_t sb = smem_u32(sm);
    const int tid = threadIdx.x, wid = tid >> 5, lane = tid & 31;
    const int warpM = wid >> 1, warpN = wid & 1;
    const int nC = blockIdx.x & 15, mtb = blockIdx.x >> 4;
    const int par = t & 1;

    uint32_t mb = sb + MB_OFF;
    if (tid == 0) { mbar_init(mb, 1); mbar_init(mb + 8, 1); mbar_init(mb + 16, 1); }
    __syncthreads();

    const __half* Zh_rd = g_Zh + (size_t)par * ZHN + (size_t)mtb * 8 * ABH;
    const __half* Zx_rd = g_Zx + (size_t)mtb * 8 * ABH;
    const char* Wbase = (const char*)(g_Wp + (size_t)nC * NKC * BBH);

    if (tid == 0) {
        #pragma unroll
        for (int s = 0; s < NSTG; s++) {
            mbar_expect(mb + s * 8, STG_BYTES);
            uint32_t as = sb + s * STG_BYTES;
            const void* asrc = (s < 8) ? (const void*)(Zx_rd + (size_t)s * ABH)
                                       : (const void*)(Zh_rd + (size_t)(s - 8) * ABH);
            bulk_cp(as, asrc, 8192u, mb + s * 8);
            bulk_cp(as + 8192u, Wbase + (size_t)s * 8192, 8192u, mb + s * 8);
        }
    }

    float acc[4][4][4];
    uint2 accl[4][4];
    #pragma unroll
    for (int a = 0; a < 4; a++)
        #pragma unroll
        for (int b = 0; b < 4; b++) {
            accl[a][b] = make_uint2(0u, 0u);
            #pragma unroll
            for (int d = 0; d < 4; d++) acc[a][b][d] = 0.f;
        }

    for (int ch = 0; ch < NKC; ch++) {
        int st = ch % NSTG;
        uint32_t ph = (uint32_t)((ch / NSTG) & 1);
        mbar_wait(mb + st * 8, ph);
        const char* stg = (const char*)sm + st * STG_BYTES;

        #pragma unroll
        for (int ks = 0; ks < 2; ks++) {
            const uint4* Ap = (const uint4*)(stg + ((ks * 8 + warpM * 4) * 32 + lane) * 16);
            uint4 a[4];
            #pragma unroll
            for (int mt = 0; mt < 4; mt++) a[mt] = Ap[mt * 32];
            const uint2* Bp = (const uint2*)(stg + 8192 + ((ks * 8 + warpN * 4) * 32 + lane) * 8);
            #pragma unroll
            for (int j = 0; j < 4; j++) {
                uint2 bh = Bp[j * 32];
                uint2 bl = Bp[512 + j * 32];
                #pragma unroll
                for (int mt = 0; mt < 4; mt++) MMA16(acc[mt][j], a[mt], bh);
                #pragma unroll
                for (int mt = 0; mt < 4; mt++) MMA16H(accl[mt][j], a[mt], bl);
            }
        }
        __syncthreads();
        if (tid == 0 && ch + NSTG < NKC) {
            int nx = ch + NSTG;
            mbar_expect(mb + st * 8, STG_BYTES);
            uint32_t as = sb + st * STG_BYTES;
            const void* asrc = (nx < 8) ? (const void*)(Zx_rd + (size_t)nx * ABH)
                                        : (const void*)(Zh_rd + (size_t)(nx - 8) * ABH);
            bulk_cp(as, asrc, 8192u, mb + st * 8);
            bulk_cp(as + 8192u, Wbase + (size_t)nx * 8192, 8192u, mb + st * 8);
        }
    }

    // fold fp16 lo accumulators into fp32
    #pragma unroll
    for (int mt = 0; mt < 4; mt++)
        #pragma unroll
        for (int j = 0; j < 4; j++) {
            __half2 p0 = *reinterpret_cast<__half2*>(&accl[mt][j].x);
            __half2 p1 = *reinterpret_cast<__half2*>(&accl[mt][j].y);
            acc[mt][j][0] += __low2float(p0);  acc[mt][j][1] += __high2float(p0);
            acc[mt][j][2] += __low2float(p1);  acc[mt][j][3] += __high2float(p1);
        }

    // ---- epilogue: LSTM cell; h written directly as next-step A fragments ---
    const int q = lane & 3, rb = lane >> 2;
    float* red = (float*)((char*)sm + RED_OFF_B);
    __half* zh_w = g_Zh + (size_t)(par ^ 1) * ZHN + (size_t)(mtb * 8 + (nC >> 1)) * ABH;
    const int ksw = nC & 1;

    #pragma unroll
    for (int mt = 0; mt < 4; mt++) {
        #pragma unroll
        for (int half = 0; half < 2; half++) {
            int row_local = warpM * 64 + mt * 16 + half * 8 + rb;
            int grow = mtb * 128 + row_local;
            int hbase = nC * 16 + warpN * 8 + 2 * q;
            float2 cold = *(const float2*)&g_c[(size_t)grow * HD + hbase];
            float coldv[2] = { cold.x, cold.y };
            float cn[2], hn[2];
            float ysum = 0.f;
            #pragma unroll
            for (int jj = 0; jj < 2; jj++) {
                int hcol = hbase + jj;
                float gi = acc[mt][0][half * 2 + 0] * 0.f; // placeholder avoided below
                (void)gi;
                float g_i = acc[mt][jj * 2 + 0][half * 2 + 0] + g_bc[hcol];
                float g_f = acc[mt][jj * 2 + 0][half * 2 + 1] + g_bc[256 + hcol];
                float g_g = acc[mt][jj * 2 + 1][half * 2 + 0] + g_bc[512 + hcol];
                float g_o = acc[mt][jj * 2 + 1][half * 2 + 1] + g_bc[768 + hcol];
                float cc = fmaf(sigm(g_f), coldv[jj], sigm(g_i) * tanhf(g_g));
                float hh = sigm(g_o) * tanhf(cc);
                cn[jj] = cc; hn[jj] = hh;
                ysum = fmaf(hh, __ldg(w_out + hcol), ysum);
            }
            *(float2*)&g_c[(size_t)grow * HD + hbase] = make_float2(cn[0], cn[1]);
            // h fragment write: u0 = ((ks*8 + m16)*32 + lane)*8 + (warpN*2 + half)*2
            int u0 = (((ksw * 8) + warpM * 4 + mt) * 32 + lane) * 8 + (warpN * 2 + half) * 2;
            *reinterpret_cast<__half2*>(zh_w + u0) =
                __halves2half2(__float2half_rn(hn[0]), __float2half_rn(hn[1]));
            ysum += __shfl_xor_sync(0xffffffffu, ysum, 1);
            ysum += __shfl_xor_sync(0xffffffffu, ysum, 2);
            if (q == 0) red[warpN * 128 + row_local] = ysum;
        }
    }
    __syncthreads();
    if (tid < 128) {
        float s = red[tid] + red[128 + tid];
        g_ypart[nC * MROWS + mtb * 128 + tid] = s;
    }
}

// ---------------- finalize: out[NT-1] ----------------------------------------
__global__ void final_kernel(const float* __restrict__ b_out, float* __restrict__ out)
{
    int i = blockIdx.x * blockDim.x + threadIdx.x;
    if (i < NG) {
        float yv = b_out[0];
        #pragma unroll
        for (int n = 0; n < NNT; n++) yv += g_ypart[n * MROWS + i];
        out[(size_t)(NTT - 1) * NG + i] = yv;
    }
}

// ---------------- launch ------------------------------------------------------
extern "C" void kernel_launch(void* const* d_in, const int* in_sizes, int n_in,
                              void* d_out, int out_size)
{
    const float* x     = (const float*)d_in[0];
    const float* y     = (const float*)d_in[1];
    const float* w_in  = (const float*)d_in[2];
    const float* b_in  = (const float*)d_in[3];
    const float* w_ih  = (const float*)d_in[4];
    const float* b_ih  = (const float*)d_in[5];
    const float* w_hh  = (const float*)d_in[6];
    const float* b_hh  = (const float*)d_in[7];
    const float* w_out = (const float*)d_in[8];
    const float* b_out = (const float*)d_in[9];
    float* out = (float*)d_out;
    (void)in_sizes; (void)n_in; (void)out_size;

    cudaFuncSetAttribute(gemm_kernel, cudaFuncAttributeMaxDynamicSharedMemorySize,
                         SMEM_BYTES);

    init_kernel<<<512, 256>>>(w_ih, b_ih, w_hh, b_hh, w_in);
    ubase_kernel<<<NTT * RB_PER_T, 256>>>(x, w_in, b_in);
    for (int t = 0; t < NTT; t++) {
        prep_kernel<<<NMT * 8, 128>>>(t, y, b_out, out);
        gemm_kernel<<<NMT * NNT, 128, SMEM_BYTES>>>(t, w_out);
    }
    final_kernel<<<(NG + 255) / 256, 256>>>(b_out, out);
}

// round 7
// speedup vs baseline: 2.6360x; 1.0159x over previous
#include <cuda_runtime.h>
#include <cuda_fp16.h>
#include <math.h>
#include <stdint.h>

#define NTT   365
#define NG    3000
#define NXI   20
#define HD    256
#define MROWS 3072               /* padded rows */
#define NMT   24                 /* M tiles of 128 */
#define NNT   16                 /* N tiles of 64 packed cols */
#define NKC   16                 /* K chunks of 32 (K=512) */
#define ABH   4096               /* halfs per A block (8KB, single fp16) */
#define BBH   4096               /* halfs per B block (8KB: hi 4KB + lo 4KB) */
#define ZXN   (NMT * 8 * ABH)    /* x-half fragment pool */
#define ZHN   (NMT * 8 * ABH)    /* h-half fragment pool (per parity buffer) */
#define UBN   ((size_t)NTT * NG * 256)
#define RB_PER_T 94              /* ceil(3000/32) row blocks for ubase */
#define STG_BYTES 16384          /* A 8KB + B 8KB */
#define NSTG  4
#define RED_OFF_B (NSTG * STG_BYTES)     /* 65536 */
#define MB_OFF (RED_OFF_B + 1024)        /* 66560 */
#define SMEM_BYTES (MB_OFF + 48)

// ---------------- persistent device globals ---------------------------------
__device__ __half g_Wp[NNT * NKC * BBH];   // fragment-ordered weights hi/lo (2MB)
__device__ __half g_Zx[ZXN];               // x0 fragments (prep-written, 1.5MB)
__device__ __half g_Zh[2 * ZHN];           // h fragments, double-buffered (3MB)
__device__ __half g_ub[UBN];               // ubase = Win_x.x + b_in, all t (561MB)
__device__ float g_bc[1024];
__device__ float g_winy[256];              // w_in[:,20]
__device__ float g_c[MROWS * HD];
__device__ float g_ypart[NNT * MROWS];

// ---------------- helpers ----------------------------------------------------
__device__ __forceinline__ float sigm(float v) { return 1.f / (1.f + __expf(-v)); }
__device__ __forceinline__ uint32_t smem_u32(const void* p) {
    uint32_t a;
    asm("{ .reg .u64 t; cvta.to.shared.u64 t, %1; cvt.u32.u64 %0, t; }" : "=r"(a) : "l"(p));
    return a;
}
__device__ __forceinline__ void mbar_init(uint32_t m, uint32_t cnt) {
    asm volatile("mbarrier.init.shared.b64 [%0], %1;" :: "r"(m), "r"(cnt) : "memory");
}
__device__ __forceinline__ void mbar_expect(uint32_t m, uint32_t b) {
    asm volatile("mbarrier.arrive.expect_tx.shared.b64 _, [%0], %1;" :: "r"(m), "r"(b) : "memory");
}
__device__ __forceinline__ void mbar_wait(uint32_t m, uint32_t ph) {
    asm volatile("{\n\t.reg .pred P;\nW1_%=:\n\t"
        "mbarrier.try_wait.parity.acquire.cta.shared::cta.b64 P, [%0], %1, 0x989680;\n\t"
        "@P bra W2_%=;\n\tbra W1_%=;\nW2_%=:\n\t}" :: "r"(m), "r"(ph) : "memory");
}
__device__ __forceinline__ void bulk_cp(uint32_t dst, const void* src, uint32_t bytes, uint32_t mbar) {
    asm volatile("cp.async.bulk.shared::cluster.global.mbarrier::complete_tx::bytes [%0], [%1], %2, [%3];"
        :: "r"(dst), "l"(src), "r"(bytes), "r"(mbar) : "memory");
}

// fp16 m16n8k16 fragment encoding (row.col), validated rounds 4-6:
//  A reg: r = (kk>=8)*2 + (row>=8); lane = (row%8)*4 + ((kk%8)>>1); slot = kk&1
//  B reg: r = kk>>3; lane = (col%8)*4 + ((kk%8)>>1); slot = kk&1
#define MMA16(d, a, b) \
    asm volatile("mma.sync.aligned.m16n8k16.row.col.f32.f16.f16.f32 " \
        "{%0,%1,%2,%3}, {%4,%5,%6,%7}, {%8,%9}, {%0,%1,%2,%3};" \
        : "+f"((d)[0]), "+f"((d)[1]), "+f"((d)[2]), "+f"((d)[3]) \
        : "r"((a).x), "r"((a).y), "r"((a).z), "r"((a).w), \
          "r"((b).x), "r"((b).y))

// ---------------- init: pack weights (fp16 hi/lo) into fragment order --------
__global__ void init_kernel(const float* __restrict__ w_ih, const float* __restrict__ b_ih,
                            const float* __restrict__ w_hh, const float* __restrict__ b_hh,
                            const float* __restrict__ w_in)
{
    int idx = blockIdx.x * blockDim.x + threadIdx.x;
    int stride = gridDim.x * blockDim.x;
    for (int i = idx; i < 512 * 1024; i += stride) {
        int k = i >> 10, P = i & 1023;
        int nC = P >> 6, Pt = P & 63;
        int wN = Pt >> 5, Pl = Pt & 31;
        int j = Pl >> 3, s = Pl & 7, q = s >> 1, e = s & 1;
        int hl = q * 2 + (j >> 1);
        int gate = (j & 1) * 2 + e;
        int hcol = nC * 16 + wN * 8 + hl;
        int row = gate * 256 + hcol;
        float val = (k < 256) ? w_ih[row * 256 + k] : w_hh[row * 256 + (k - 256)];
        __half hb = __float2half_rn(val);
        __half lb = __float2half_rn(val - __half2float(hb));
        int ch = k >> 5, ks = (k >> 4) & 1, kk = k & 15;
        int nt8 = Pt >> 3;
        int lane = s * 4 + ((kk & 7) >> 1);
        int u = ((ks * 8 + nt8) * 32 + lane) * 4 + (kk >> 3) * 2 + (kk & 1);
        __half* wb = g_Wp + (size_t)(nC * NKC + ch) * BBH;
        wb[u] = hb;
        wb[2048 + u] = lb;
    }
    for (int i = idx; i < 1024; i += stride) g_bc[i] = b_ih[i] + b_hh[i];
    for (int i = idx; i < 256; i += stride) g_winy[i] = w_in[i * 21 + 20];
    for (int i = idx; i < MROWS * HD; i += stride) g_c[i] = 0.f;
    for (int i = idx; i < NNT * MROWS; i += stride) g_ypart[i] = 0.f;
    uint32_t* zh = (uint32_t*)g_Zh;
    for (int i = idx; i < ZHN; i += stride) zh[i] = 0u;   // both parity buffers
}

// ---------------- ubase: Win_x . x + b_in for ALL timesteps ------------------
__global__ void __launch_bounds__(256) ubase_kernel(
    const float* __restrict__ x, const float* __restrict__ w_in,
    const float* __restrict__ b_in)
{
    __shared__ float wsm[256 * 21];
    __shared__ float xsm[32 * NXI];
    int b = blockIdx.x;
    int t = b / RB_PER_T, rb = b % RB_PER_T;
    int r0 = rb * 32;
    int tid = threadIdx.x;
    for (int i = tid; i < 256 * 21; i += 256) wsm[i] = w_in[i];
    for (int i = tid; i < 32 * NXI; i += 256) {
        int rr = i / NXI, d = i % NXI;
        int row = r0 + rr;
        xsm[i] = (row < NG) ? x[((size_t)t * NG + row) * NXI + d] : 0.f;
    }
    __syncthreads();
    int col = tid;
    float w[NXI];
    #pragma unroll
    for (int d = 0; d < NXI; d++) w[d] = wsm[col * 21 + d];
    float bb = b_in[col];
    #pragma unroll 2
    for (int rr = 0; rr < 32; rr++) {
        int row = r0 + rr;
        if (row >= NG) break;
        float s = bb;
        #pragma unroll
        for (int d = 0; d < NXI; d++) s = fmaf(xsm[rr * NXI + d], w[d], s);
        g_ub[((size_t)t * NG + row) * 256 + col] = __float2half_rn(s);
    }
}

// ---------------- prep: x0 = relu(ubase + yt*winy) as fragments --------------
__global__ void __launch_bounds__(128) prep_kernel(
    int t, const float* __restrict__ y, const float* __restrict__ b_out,
    float* __restrict__ out)
{
    __shared__ __half stg[ABH];
    int mt = blockIdx.x >> 3, kc = blockIdx.x & 7;
    int r = threadIdx.x;
    int gr = mt * 128 + r;
    bool valid = gr < NG;
    float v[32];

    float yt = 0.f;
    if (valid) {
        float yprev = 0.f;
        if (t > 0) {
            #pragma unroll
            for (int n = 0; n < NNT; n++) yprev += g_ypart[n * MROWS + gr];
            yprev += b_out[0];
            if (kc == 0) out[(size_t)(t - 1) * NG + gr] = yprev;
        }
        float yobs = y[(size_t)t * NG + gr];
        yt = (yobs == yobs) ? yobs : yprev;      // fillObs
        const __half* up = g_ub + ((size_t)t * NG + gr) * 256 + kc * 32;
        #pragma unroll
        for (int c = 0; c < 32; c++)
            v[c] = fmaxf(__half2float(up[c]) + yt * g_winy[kc * 32 + c], 0.f);
    } else {
        #pragma unroll
        for (int c = 0; c < 32; c++) v[c] = 0.f;
    }

    int m16 = r >> 4, rl = r & 15, rq = rl & 7, half = rl >> 3;
    #pragma unroll
    for (int c = 0; c < 32; c++) {
        int ks = c >> 4, kk = c & 15;
        int lane = rq * 4 + ((kk & 7) >> 1);
        int reg = ((kk >> 3) << 1) + half;
        int u = ((ks * 8 + m16) * 32 + lane) * 8 + reg * 2 + (kk & 1);
        stg[u] = __float2half_rn(v[c]);
    }
    __syncthreads();
    const uint4* s4 = (const uint4*)stg;
    uint4* d4 = (uint4*)(g_Zx + (size_t)(mt * 8 + kc) * ABH);
    #pragma unroll
    for (int i = r; i < 512; i += 128) d4[i] = s4[i];
}

// ---------------- GEMM + LSTM cell: fp16 2-pass, both f32-acc ----------------
// grid = 384 CTAs (24 M x 16 N), 128 threads (4 warps: 2M x 2N, warp 64x32)
__global__ void __launch_bounds__(128) gemm_kernel(int t, const float* __restrict__ w_out)
{
    extern __shared__ float sm[];
    uint32_t sb = smem_u32(sm);
    const int tid = threadIdx.x, wid = tid >> 5, lane = tid & 31;
    const int warpM = wid >> 1, warpN = wid & 1;
    const int nC = blockIdx.x & 15, mtb = blockIdx.x >> 4;
    const int par = t & 1;

    uint32_t mb = sb + MB_OFF;
    if (tid == 0) {
        #pragma unroll
        for (int s = 0; s < NSTG; s++) mbar_init(mb + s * 8, 1);
    }
    __syncthreads();

    const __half* Zh_rd = g_Zh + (size_t)par * ZHN + (size_t)mtb * 8 * ABH;
    const __half* Zx_rd = g_Zx + (size_t)mtb * 8 * ABH;
    const char* Wbase = (const char*)(g_Wp + (size_t)nC * NKC * BBH);

    if (tid == 0) {
        #pragma unroll
        for (int s = 0; s < NSTG; s++) {
            mbar_expect(mb + s * 8, STG_BYTES);
            uint32_t as = sb + s * STG_BYTES;
            const void* asrc = (s < 8) ? (const void*)(Zx_rd + (size_t)s * ABH)
                                       : (const void*)(Zh_rd + (size_t)(s - 8) * ABH);
            bulk_cp(as, asrc, 8192u, mb + s * 8);
            bulk_cp(as + 8192u, Wbase + (size_t)s * 8192, 8192u, mb + s * 8);
        }
    }

    float acc[4][4][4];
    #pragma unroll
    for (int a = 0; a < 4; a++)
        #pragma unroll
        for (int b = 0; b < 4; b++)
            #pragma unroll
            for (int d = 0; d < 4; d++) acc[a][b][d] = 0.f;

    for (int ch = 0; ch < NKC; ch++) {
        int st = ch % NSTG;
        uint32_t ph = (uint32_t)((ch / NSTG) & 1);
        mbar_wait(mb + st * 8, ph);
        const char* stg = (const char*)sm + st * STG_BYTES;

        #pragma unroll
        for (int ks = 0; ks < 2; ks++) {
            const uint4* Ap = (const uint4*)(stg + ((ks * 8 + warpM * 4) * 32 + lane) * 16);
            uint4 a[4];
            #pragma unroll
            for (int mt = 0; mt < 4; mt++) a[mt] = Ap[mt * 32];
            const uint2* Bp = (const uint2*)(stg + 8192 + ((ks * 8 + warpN * 4) * 32 + lane) * 8);
            #pragma unroll
            for (int j = 0; j < 4; j++) {
                uint2 bh = Bp[j * 32];
                uint2 bl = Bp[512 + j * 32];
                #pragma unroll
                for (int mt = 0; mt < 4; mt++) MMA16(acc[mt][j], a[mt], bh);
                #pragma unroll
                for (int mt = 0; mt < 4; mt++) MMA16(acc[mt][j], a[mt], bl);
            }
        }
        __syncthreads();
        if (tid == 0 && ch + NSTG < NKC) {
            int nx = ch + NSTG;
            mbar_expect(mb + st * 8, STG_BYTES);
            uint32_t as = sb + st * STG_BYTES;
            const void* asrc = (nx < 8) ? (const void*)(Zx_rd + (size_t)nx * ABH)
                                        : (const void*)(Zh_rd + (size_t)(nx - 8) * ABH);
            bulk_cp(as, asrc, 8192u, mb + st * 8);
            bulk_cp(as + 8192u, Wbase + (size_t)nx * 8192, 8192u, mb + st * 8);
        }
    }

    // ---- epilogue: LSTM cell; h written directly as next-step A fragments ---
    const int q = lane & 3, rb = lane >> 2;
    float* red = (float*)((char*)sm + RED_OFF_B);
    __half* zh_w = g_Zh + (size_t)(par ^ 1) * ZHN + (size_t)(mtb * 8 + (nC >> 1)) * ABH;
    const int ksw = nC & 1;

    #pragma unroll
    for (int mt = 0; mt < 4; mt++) {
        #pragma unroll
        for (int half = 0; half < 2; half++) {
            int row_local = warpM * 64 + mt * 16 + half * 8 + rb;
            int grow = mtb * 128 + row_local;
            int hbase = nC * 16 + warpN * 8 + 2 * q;
            float2 cold = *(const float2*)&g_c[(size_t)grow * HD + hbase];
            float coldv[2] = { cold.x, cold.y };
            float cn[2], hn[2];
            float ysum = 0.f;
            #pragma unroll
            for (int jj = 0; jj < 2; jj++) {
                int hcol = hbase + jj;
                float g_i = acc[mt][jj * 2 + 0][half * 2 + 0] + g_bc[hcol];
                float g_f = acc[mt][jj * 2 + 0][half * 2 + 1] + g_bc[256 + hcol];
                float g_g = acc[mt][jj * 2 + 1][half * 2 + 0] + g_bc[512 + hcol];
                float g_o = acc[mt][jj * 2 + 1][half * 2 + 1] + g_bc[768 + hcol];
                float cc = fmaf(sigm(g_f), coldv[jj], sigm(g_i) * tanhf(g_g));
                float hh = sigm(g_o) * tanhf(cc);
                cn[jj] = cc; hn[jj] = hh;
                ysum = fmaf(hh, __ldg(w_out + hcol), ysum);
            }
            *(float2*)&g_c[(size_t)grow * HD + hbase] = make_float2(cn[0], cn[1]);
            int u0 = (((ksw * 8) + warpM * 4 + mt) * 32 + lane) * 8 + (warpN * 2 + half) * 2;
            *reinterpret_cast<__half2*>(zh_w + u0) =
                __halves2half2(__float2half_rn(hn[0]), __float2half_rn(hn[1]));
            ysum += __shfl_xor_sync(0xffffffffu, ysum, 1);
            ysum += __shfl_xor_sync(0xffffffffu, ysum, 2);
            if (q == 0) red[warpN * 128 + row_local] = ysum;
        }
    }
    __syncthreads();
    if (tid < 128) {
        float s = red[tid] + red[128 + tid];
        g_ypart[nC * MROWS + mtb * 128 + tid] = s;
    }
}

// ---------------- finalize: out[NT-1] ----------------------------------------
__global__ void final_kernel(const float* __restrict__ b_out, float* __restrict__ out)
{
    int i = blockIdx.x * blockDim.x + threadIdx.x;
    if (i < NG) {
        float yv = b_out[0];
        #pragma unroll
        for (int n = 0; n < NNT; n++) yv += g_ypart[n * MROWS + i];
        out[(size_t)(NTT - 1) * NG + i] = yv;
    }
}

// ---------------- launch ------------------------------------------------------
extern "C" void kernel_launch(void* const* d_in, const int* in_sizes, int n_in,
                              void* d_out, int out_size)
{
    const float* x     = (const float*)d_in[0];
    const float* y     = (const float*)d_in[1];
    const float* w_in  = (const float*)d_in[2];
    const float* b_in  = (const float*)d_in[3];
    const float* w_ih  = (const float*)d_in[4];
    const float* b_ih  = (const float*)d_in[5];
    const float* w_hh  = (const float*)d_in[6];
    const float* b_hh  = (const float*)d_in[7];
    const float* w_out = (const float*)d_in[8];
    const float* b_out = (const float*)d_in[9];
    float* out = (float*)d_out;
    (void)in_sizes; (void)n_in; (void)out_size;

    cudaFuncSetAttribute(gemm_kernel, cudaFuncAttributeMaxDynamicSharedMemorySize,
                         SMEM_BYTES);

    init_kernel<<<512, 256>>>(w_ih, b_ih, w_hh, b_hh, w_in);
    ubase_kernel<<<NTT * RB_PER_T, 256>>>(x, w_in, b_in);
    for (int t = 0; t < NTT; t++) {
        prep_kernel<<<NMT * 8, 128>>>(t, y, b_out, out);
        gemm_kernel<<<NMT * NNT, 128, SMEM_BYTES>>>(t, w_out);
    }
    final_kernel<<<(NG + 255) / 256, 256>>>(b_out, out);
}